// round 17
// baseline (speedup 1.0000x reference)
#include <cuda_runtime.h>

#define SK_N      512
#define SK_ITERS  21
#define SK_THR    704          // 22 warps; reg cap 65536/704 = 93 = current usage
#define SK_NWARP  22
#define SK_NCLUST 64           // 64 clusters x 2 CTAs = 128 CTAs; 64MB hot set << L2
#define SK_ROWS_PER_CTA 256
#define SK_K2     144.26950408889634f   // 100 * log2(e): work in log2 domain
#define SK_CONV   1.52587890625e-05f    // 2^-16 per-iter v-change threshold
#define SK_B      112.0f                // exponent bias: term reach z-u > -238
#define SK_2B     5.192296858534828e33f // 2^112
#define SK_FLOOR  1.2446e-35f           // 2^-116 colp init (=> fallback dv ~ -222)

typedef unsigned long long sk_u64;

__device__ __forceinline__ float ex2f_(float x) {
    float r; asm("ex2.approx.ftz.f32 %0, %1;" : "=f"(r) : "f"(x)); return r;
}
__device__ __forceinline__ float lg2f_(float x) {
    float r; asm("lg2.approx.ftz.f32 %0, %1;" : "=f"(r) : "f"(x)); return r;
}
__device__ __forceinline__ float rcpf_(float x) {
    float r; asm("rcp.approx.ftz.f32 %0, %1;" : "=f"(r) : "f"(x)); return r;
}
// monotonic float<->uint order transform (EXACT warp max via __reduce_max_sync)
__device__ __forceinline__ unsigned f2ord(float f) {
    unsigned b = __float_as_uint(f);
    return b ^ (unsigned)(((int)b >> 31) | 0x80000000);
}
__device__ __forceinline__ float ord2f(unsigned k) {
    return __uint_as_float(k ^ (unsigned)((~(int)k >> 31) | 0x80000000));
}
// ---- packed f32x2 (Blackwell; ptxas never auto-fuses these) ----
__device__ __forceinline__ sk_u64 pk2_(float lo, float hi) {
    sk_u64 r; asm("mov.b64 %0, {%1, %2};" : "=l"(r) : "f"(lo), "f"(hi)); return r;
}
__device__ __forceinline__ void up2_(sk_u64 p, float& lo, float& hi) {
    asm("mov.b64 {%0, %1}, %2;" : "=f"(lo), "=f"(hi) : "l"(p));
}
__device__ __forceinline__ sk_u64 fma2_(sk_u64 a, sk_u64 b, sk_u64 c) {
    sk_u64 r; asm("fma.rn.f32x2 %0, %1, %2, %3;" : "=l"(r) : "l"(a), "l"(b), "l"(c)); return r;
}
__device__ __forceinline__ sk_u64 add2_(sk_u64 a, sk_u64 b) {
    sk_u64 r; asm("add.rn.f32x2 %0, %1, %2;" : "=l"(r) : "l"(a), "l"(b)); return r;
}
__device__ __forceinline__ unsigned cluster_rank_() {
    unsigned r; asm("mov.u32 %0, %%cluster_ctarank;" : "=r"(r)); return r;
}
// map a local shared address into the peer CTA's shared space (loop-invariant)
__device__ __forceinline__ unsigned mapa_peer_(unsigned addr, unsigned peer) {
    unsigned r;
    asm("mapa.shared::cluster.u32 %0, %1, %2;" : "=r"(r) : "r"(addr), "r"(peer));
    return r;
}
__device__ __forceinline__ void st_cluster_f32_(unsigned mapped_addr, float v) {
    asm volatile("st.shared::cluster.f32 [%0], %1;" :: "r"(mapped_addr), "f"(v) : "memory");
}
__device__ __forceinline__ void cluster_sync_() {
    asm volatile("barrier.cluster.arrive.aligned;" ::: "memory");
    asm volatile("barrier.cluster.wait.aligned;"   ::: "memory");
}

// SMEM floats: nv[512] (= -v) | M_s[512] | S_s[512] | stg_p[22*512] | pex[2*512]
#define OFF_V    0
#define OFF_M    512
#define OFF_S    1024
#define OFF_SP   1536
#define OFF_PEX  (1536 + SK_NWARP*512)
#define SK_SMEM_FLOATS (1536 + SK_NWARP*512 + 1024)
#define SK_SMEM_BYTES  (SK_SMEM_FLOATS * 4)

// Cluster of 2 CTAs per matrix; 64 concurrent matrices L2-resident.
// R16 structure (nv in regs, exact redux max, packed f32x2, exponent bias,
// depth-1 row prefetch) at 22 warps (reg cap == natural usage), prefetched
// output pass, and hoisted peer-address mapping.
//   Mb = M-112; t = exp2(z-Mb) (<=2^112); S2 = sum t
//   colp += t * (rcp(S2)*2^112);  u = Mb + log2(S2) (deferred to output)
//   nv_j -= (log2(P_local+P_peer) - 112)
__global__ void __launch_bounds__(SK_THR, 1) __cluster_dims__(2, 1, 1)
sinkhorn_fused(const float* __restrict__ x, float* __restrict__ out, int nmat)
{
    extern __shared__ float smem[];
    float* v_s   = smem + OFF_V;     // holds -v
    float* M_s   = smem + OFF_M;
    float* S_s   = smem + OFF_S;
    float* stg_p = smem + OFF_SP;
    float* pex   = smem + OFF_PEX;
    const unsigned smem_b = (unsigned)__cvta_generic_to_shared(smem);

    const int tid  = threadIdx.x;
    const int lane = tid & 31;
    const int wid  = tid >> 5;                 // 0..21
    const unsigned FULL = 0xffffffffu;
    const unsigned rank = cluster_rank_();
    const unsigned peer = rank ^ 1u;
    const int row0 = (int)rank * SK_ROWS_PER_CTA;
    const sk_u64 K2_2 = pk2_(SK_K2, SK_K2);

    // peer exchange addresses (loop-invariant; mapa hoisted out of iterations)
    unsigned pex_peer[2] = {0u, 0u};
    if (tid < SK_N) {
        pex_peer[0] = mapa_peer_(smem_b + (OFF_PEX + tid) * 4, peer);
        pex_peer[1] = mapa_peer_(smem_b + (OFF_PEX + 512 + tid) * 4, peer);
    }

    // 256 rows over 22 warps: warps 0-13 take 12 rows, warps 14-21 take 11
    const int nrows = (wid < 14) ? 12 : 11;
    const int rwoff = (wid < 14) ? wid * 12 : 168 + (wid - 14) * 11;

    const int cid    = blockIdx.x >> 1;
    const int nclust = gridDim.x >> 1;

    for (int m = cid; m < nmat; m += nclust) {
        const float* __restrict__ X = x   + (size_t)m * SK_N * SK_N;
        float*       __restrict__ O = out + (size_t)m * SK_N * SK_N;

        if (tid < SK_N) v_s[tid] = 0.0f;
        __syncthreads();

        for (int it = 0; it < SK_ITERS; ++it) {
            const int par = it & 1;

            // hoist nv into packed registers ONCE per iteration
            sk_u64 colv2[8];
            {
                const float4* vr = reinterpret_cast<const float4*>(v_s);
                #pragma unroll
                for (int k = 0; k < 4; ++k) {
                    float4 nv = vr[lane + 32 * k];
                    colv2[2*k]   = pk2_(nv.x, nv.y);
                    colv2[2*k+1] = pk2_(nv.z, nv.w);
                }
            }
            // floor init: dead columns still yield P > 0 (self-corrects;
            // v_new is analytically independent of v_old)
            sk_u64 colp2[8];
            const sk_u64 FLOOR2 = pk2_(SK_FLOOR, SK_FLOOR);
            #pragma unroll
            for (int e = 0; e < 8; ++e) colp2[e] = FLOOR2;

            const int rbase = row0 + rwoff;

            // depth-1 prefetch: row rbase loaded before the loop
            float4 pf[4];
            {
                const float4* x0 = reinterpret_cast<const float4*>(X + (size_t)rbase * SK_N);
                #pragma unroll
                for (int k = 0; k < 4; ++k) pf[k] = __ldg(x0 + lane + 32 * k);
            }

            #pragma unroll 1
            for (int rr = 0; rr < nrows; ++rr) {
                const int r = rbase + rr;

                // consume prefetch into z = s + nv (packed fma)
                sk_u64 z2[8];
                #pragma unroll
                for (int k = 0; k < 4; ++k) {
                    z2[2*k]   = fma2_(pk2_(pf[k].x, pf[k].y), K2_2, colv2[2*k]);
                    z2[2*k+1] = fma2_(pk2_(pf[k].z, pf[k].w), K2_2, colv2[2*k+1]);
                }
                // issue next row's loads NOW — they fly during the reduction
                if (rr + 1 < nrows) {
                    const float4* xn = reinterpret_cast<const float4*>(X + (size_t)(r + 1) * SK_N);
                    #pragma unroll
                    for (int k = 0; k < 4; ++k) pf[k] = __ldg(xn + lane + 32 * k);
                }

                // exact row max: local fmnmx chain + single REDUX
                float ml = -3.0e38f;
                #pragma unroll
                for (int e = 0; e < 8; ++e) {
                    float a, b; up2_(z2[e], a, b);
                    ml = fmaxf(ml, fmaxf(a, b));
                }
                const float M = ord2f(__reduce_max_sync(FULL, f2ord(ml)));

                // biased exp + packed sum: t = exp2(z - (M-112)) <= 2^112
                const sk_u64 mMb2 = pk2_(SK_B - M, SK_B - M);
                sk_u64 s2acc = pk2_(0.0f, 0.0f);
                #pragma unroll
                for (int e = 0; e < 8; ++e) {
                    sk_u64 w = add2_(z2[e], mMb2);
                    float a, b; up2_(w, a, b);
                    sk_u64 t = pk2_(ex2f_(a), ex2f_(b));
                    z2[e] = t;
                    s2acc = add2_(s2acc, t);
                }
                float sl, sh; up2_(s2acc, sl, sh);
                float S2 = sl + sh;
                #pragma unroll
                for (int o = 16; o > 0; o >>= 1)
                    S2 += __shfl_xor_sync(FULL, S2, o);

                // S2 in [2^112, 2^121]; rcp stays normal
                const float invSb = rcpf_(S2) * SK_2B;
                if (lane == 0) { M_s[r] = M - SK_B; S_s[r] = S2; }

                // colp += exp2(z - u + 112)  (packed fma)
                const sk_u64 inv2 = pk2_(invSb, invSb);
                #pragma unroll
                for (int e = 0; e < 8; ++e)
                    colp2[e] = fma2_(z2[e], inv2, colp2[e]);
            }

            // stage per-warp column partials (conflict-free float4)
            {
                float4* sp = reinterpret_cast<float4*>(stg_p + wid * 512);
                #pragma unroll
                for (int k = 0; k < 4; ++k) {
                    float4 o4;
                    up2_(colp2[2*k],   o4.x, o4.y);
                    up2_(colp2[2*k+1], o4.z, o4.w);
                    sp[lane + 32 * k] = o4;
                }
            }
            __syncthreads();

            // combine: thread j (< 512) owns column j over 22 warp partials
            float dv = 0.0f;
            float Pl = 0.0f;
            if (tid < SK_N) {
                #pragma unroll
                for (int w = 0; w < SK_NWARP; ++w) Pl += stg_p[w * 512 + tid];
                st_cluster_f32_(pex_peer[par], Pl);
            }
            cluster_sync_();   // release our DSMEM store / acquire peer's
            if (tid < SK_N) {
                const float P = Pl + pex[par * 512 + tid];   // > 0 by floor
                dv = lg2f_(P) - SK_B;
                v_s[tid] -= dv;          // nv convention: nv -= dv
            }
            const int active = __syncthreads_count(fabsf(dv) > SK_CONV);
            if (active == 0) break;   // identical in both CTAs -> coherent exit
        }

        // output: exp2(s + nv - u), u = Mb + log2(S2); packed, streaming,
        // depth-1 prefetched like the main loop
        {
            sk_u64 colv2[8];
            const float4* vr = reinterpret_cast<const float4*>(v_s);
            #pragma unroll
            for (int k = 0; k < 4; ++k) {
                float4 nv = vr[lane + 32 * k];
                colv2[2*k]   = pk2_(nv.x, nv.y);
                colv2[2*k+1] = pk2_(nv.z, nv.w);
            }
            const int rbase = row0 + rwoff;
            float4 pf[4];
            {
                const float4* x0 = reinterpret_cast<const float4*>(X + (size_t)rbase * SK_N);
                #pragma unroll
                for (int k = 0; k < 4; ++k) pf[k] = __ldcs(x0 + lane + 32 * k);
            }
            #pragma unroll 1
            for (int rr = 0; rr < nrows; ++rr) {
                const int r = rbase + rr;
                const float ur = M_s[r] + lg2f_(S_s[r]);   // true u (bias cancels)
                const sk_u64 mu2 = pk2_(-ur, -ur);
                float4 xv[4];
                #pragma unroll
                for (int k = 0; k < 4; ++k) xv[k] = pf[k];
                if (rr + 1 < nrows) {
                    const float4* xn = reinterpret_cast<const float4*>(X + (size_t)(r + 1) * SK_N);
                    #pragma unroll
                    for (int k = 0; k < 4; ++k) pf[k] = __ldcs(xn + lane + 32 * k);
                }
                float4* orow = reinterpret_cast<float4*>(O + (size_t)r * SK_N);
                #pragma unroll
                for (int k = 0; k < 4; ++k) {
                    sk_u64 a2 = add2_(fma2_(pk2_(xv[k].x, xv[k].y), K2_2, colv2[2*k]),   mu2);
                    sk_u64 b2 = add2_(fma2_(pk2_(xv[k].z, xv[k].w), K2_2, colv2[2*k+1]), mu2);
                    float4 o;
                    { float a, b; up2_(a2, a, b); o.x = ex2f_(a); o.y = ex2f_(b); }
                    { float a, b; up2_(b2, a, b); o.z = ex2f_(a); o.w = ex2f_(b); }
                    __stcs(orow + lane + 32 * k, o);
                }
            }
        }
        // protect exchange buffers + v_s before the next matrix starts
        cluster_sync_();
        __syncthreads();
    }
}

extern "C" void kernel_launch(void* const* d_in, const int* in_sizes, int n_in,
                              void* d_out, int out_size)
{
    const float* x = (const float*)d_in[0];
    float* out = (float*)d_out;
    const int nmat = in_sizes[0] / (SK_N * SK_N);

    cudaFuncSetAttribute(sinkhorn_fused,
                         cudaFuncAttributeMaxDynamicSharedMemorySize, SK_SMEM_BYTES);

    int nclust = nmat < SK_NCLUST ? nmat : SK_NCLUST;
    sinkhorn_fused<<<2 * nclust, SK_THR, SK_SMEM_BYTES>>>(x, out, nmat);
}